// round 3
// baseline (speedup 1.0000x reference)
#include <cuda_runtime.h>
#include <cuda_bf16.h>
#include <cstdint>

#define N_NODES 100000
#define N_EDGES 1000000
#define D 64

// ---------------------------------------------------------------------------
// Scratch (__device__ globals; no allocation allowed)
// ---------------------------------------------------------------------------
__device__ float g_agg[N_NODES * D];     // h before MLP
__device__ int   g_count[N_NODES];       // degree histogram, then reused as cursor
__device__ int   g_off[N_NODES + 1];     // CSR offsets
__device__ int   g_src[N_EDGES];         // CSR src lists (grouped by dst)

// ---------------------------------------------------------------------------
// K1: zero counts
// ---------------------------------------------------------------------------
__global__ void zero_kernel(int* __restrict__ cnt) {
    int i = blockIdx.x * blockDim.x + threadIdx.x;
    if (i < N_NODES) cnt[i] = 0;
}

// ---------------------------------------------------------------------------
// K2: histogram of dst
// ---------------------------------------------------------------------------
__global__ void hist_kernel(const int* __restrict__ ei, int* __restrict__ cnt) {
    int e = blockIdx.x * blockDim.x + threadIdx.x;
    if (e < N_EDGES) {
        int dst = ei[N_EDGES + e];
        if ((unsigned)dst < N_NODES) atomicAdd(&cnt[dst], 1);
    }
}

// ---------------------------------------------------------------------------
// K3: exclusive scan of degrees -> offsets; zero counts for cursor reuse.
// Single block, 1024 threads, chunked serial + Hillis-Steele over partials.
// ---------------------------------------------------------------------------
#define SCAN_T 1024
#define CHUNK  98   // 1024*98 = 100352 >= 100000

__global__ __launch_bounds__(SCAN_T)
void scan_kernel(int* __restrict__ cnt, int* __restrict__ off) {
    __shared__ int sp[SCAN_T];
    int t = threadIdx.x;
    int lo = t * CHUNK;
    int hi = min(lo + CHUNK, N_NODES);

    int sum = 0;
    for (int i = lo; i < hi; i++) sum += cnt[i];
    sp[t] = sum;

    // inclusive Hillis-Steele
    for (int ofs = 1; ofs < SCAN_T; ofs <<= 1) {
        __syncthreads();
        int v = (t >= ofs) ? sp[t - ofs] : 0;
        __syncthreads();
        sp[t] += v;
    }
    __syncthreads();
    int running = sp[t] - sum;   // exclusive prefix of this chunk

    for (int i = lo; i < hi; i++) {
        int c = cnt[i];
        off[i] = running;
        running += c;
        cnt[i] = 0;              // reset for cursor use in fill
    }
    if (t == 0) off[N_NODES] = N_EDGES;
}

// ---------------------------------------------------------------------------
// K4: fill CSR src lists
// ---------------------------------------------------------------------------
__global__ void fill_kernel(const int* __restrict__ ei,
                            const int* __restrict__ off,
                            int* __restrict__ cur,
                            int* __restrict__ csr_src) {
    int e = blockIdx.x * blockDim.x + threadIdx.x;
    if (e < N_EDGES) {
        int src = ei[e];
        int dst = ei[N_EDGES + e];
        if ((unsigned)src >= N_NODES || (unsigned)dst >= N_NODES) return;
        int pos = off[dst] + atomicAdd(&cur[dst], 1);
        csr_src[pos] = src;
    }
}

// ---------------------------------------------------------------------------
// K5: gather + fused (1+eps)*x init. One warp per node; lane owns a float2.
// Each agg row written exactly once; zero float atomics.
// ---------------------------------------------------------------------------
__global__ __launch_bounds__(256)
void gather_kernel(const float2* __restrict__ x2,
                   const float* __restrict__ eps,
                   const int* __restrict__ off,
                   const int* __restrict__ csr_src,
                   float2* __restrict__ agg2) {
    int warp = (blockIdx.x * blockDim.x + threadIdx.x) >> 5;
    int lane = threadIdx.x & 31;
    if (warp >= N_NODES) return;

    float s = 1.0f + *eps;
    float2 v = x2[(long long)warp * 32 + lane];
    float ax = s * v.x, ay = s * v.y;

    int k   = off[warp];
    int end = off[warp + 1];
    // unroll-by-2 for a bit of MLP on the dependent src->x chain
    for (; k + 2 <= end; k += 2) {
        int s0 = csr_src[k];
        int s1 = csr_src[k + 1];
        float2 n0 = x2[(long long)s0 * 32 + lane];
        float2 n1 = x2[(long long)s1 * 32 + lane];
        ax += n0.x + n1.x;
        ay += n0.y + n1.y;
    }
    if (k < end) {
        int s0 = csr_src[k];
        float2 n0 = x2[(long long)s0 * 32 + lane];
        ax += n0.x;
        ay += n0.y;
    }
    float2 o; o.x = ax; o.y = ay;
    agg2[(long long)warp * 32 + lane] = o;
}

// ---------------------------------------------------------------------------
// K6: fused 2-layer MLP with LeakyReLU (unchanged from R2).
// ---------------------------------------------------------------------------
#define MLP_ROWS 64
#define XS_STRIDE 66

__device__ __forceinline__ float leaky(float v) {
    return fmaxf(v, 0.01f * v);
}

__global__ __launch_bounds__(256, 2)
void mlp_kernel(const float* __restrict__ agg,
                const float* __restrict__ W1, const float* __restrict__ b1,
                const float* __restrict__ W2, const float* __restrict__ b2,
                float* __restrict__ out) {
    __shared__ float Xs[MLP_ROWS][XS_STRIDE];
    __shared__ float Ws[D][D];
    __shared__ float bs[D];

    const int tid = threadIdx.x;
    const int cg  = tid & 7;
    const int rg  = tid >> 3;
    const int row_base = blockIdx.x * MLP_ROWS;

    {
        const float2* src = (const float2*)(agg + (long long)row_base * D);
        for (int idx = tid; idx < MLP_ROWS * (D / 2); idx += 256) {
            int r = idx >> 5;
            int p = idx & 31;
            float2 v;
            if (row_base + r < N_NODES) v = src[r * 32 + p];
            else { v.x = 0.f; v.y = 0.f; }
            Xs[r][p * 2]     = v.x;
            Xs[r][p * 2 + 1] = v.y;
        }
    }
    {
        const float4* w = (const float4*)W1;
        float4* ws = (float4*)&Ws[0][0];
        for (int idx = tid; idx < D * D / 4; idx += 256) ws[idx] = w[idx];
        if (tid < D) bs[tid] = b1[tid];
    }
    __syncthreads();

    const int r0 = rg * 2;
    const int c0 = cg * 8;

    float acc[2][8];
    #pragma unroll
    for (int j = 0; j < 8; j++) { acc[0][j] = bs[c0 + j]; acc[1][j] = bs[c0 + j]; }

    #pragma unroll 8
    for (int k = 0; k < D; k++) {
        float x0 = Xs[r0][k];
        float x1 = Xs[r0 + 1][k];
        float4 wlo = *(const float4*)&Ws[k][c0];
        float4 whi = *(const float4*)&Ws[k][c0 + 4];
        acc[0][0] = fmaf(x0, wlo.x, acc[0][0]); acc[1][0] = fmaf(x1, wlo.x, acc[1][0]);
        acc[0][1] = fmaf(x0, wlo.y, acc[0][1]); acc[1][1] = fmaf(x1, wlo.y, acc[1][1]);
        acc[0][2] = fmaf(x0, wlo.z, acc[0][2]); acc[1][2] = fmaf(x1, wlo.z, acc[1][2]);
        acc[0][3] = fmaf(x0, wlo.w, acc[0][3]); acc[1][3] = fmaf(x1, wlo.w, acc[1][3]);
        acc[0][4] = fmaf(x0, whi.x, acc[0][4]); acc[1][4] = fmaf(x1, whi.x, acc[1][4]);
        acc[0][5] = fmaf(x0, whi.y, acc[0][5]); acc[1][5] = fmaf(x1, whi.y, acc[1][5]);
        acc[0][6] = fmaf(x0, whi.z, acc[0][6]); acc[1][6] = fmaf(x1, whi.z, acc[1][6]);
        acc[0][7] = fmaf(x0, whi.w, acc[0][7]); acc[1][7] = fmaf(x1, whi.w, acc[1][7]);
    }
    __syncthreads();

    #pragma unroll
    for (int i = 0; i < 2; i++)
        #pragma unroll
        for (int j = 0; j < 8; j++)
            Xs[r0 + i][c0 + j] = leaky(acc[i][j]);

    {
        const float4* w = (const float4*)W2;
        float4* ws = (float4*)&Ws[0][0];
        for (int idx = tid; idx < D * D / 4; idx += 256) ws[idx] = w[idx];
        if (tid < D) bs[tid] = b2[tid];
    }
    __syncthreads();

    #pragma unroll
    for (int j = 0; j < 8; j++) { acc[0][j] = bs[c0 + j]; acc[1][j] = bs[c0 + j]; }

    #pragma unroll 8
    for (int k = 0; k < D; k++) {
        float x0 = Xs[r0][k];
        float x1 = Xs[r0 + 1][k];
        float4 wlo = *(const float4*)&Ws[k][c0];
        float4 whi = *(const float4*)&Ws[k][c0 + 4];
        acc[0][0] = fmaf(x0, wlo.x, acc[0][0]); acc[1][0] = fmaf(x1, wlo.x, acc[1][0]);
        acc[0][1] = fmaf(x0, wlo.y, acc[0][1]); acc[1][1] = fmaf(x1, wlo.y, acc[1][1]);
        acc[0][2] = fmaf(x0, wlo.z, acc[0][2]); acc[1][2] = fmaf(x1, wlo.z, acc[1][2]);
        acc[0][3] = fmaf(x0, wlo.w, acc[0][3]); acc[1][3] = fmaf(x1, wlo.w, acc[1][3]);
        acc[0][4] = fmaf(x0, whi.x, acc[0][4]); acc[1][4] = fmaf(x1, whi.x, acc[1][4]);
        acc[0][5] = fmaf(x0, whi.y, acc[0][5]); acc[1][5] = fmaf(x1, whi.y, acc[1][5]);
        acc[0][6] = fmaf(x0, whi.z, acc[0][6]); acc[1][6] = fmaf(x1, whi.z, acc[1][6]);
        acc[0][7] = fmaf(x0, whi.w, acc[0][7]); acc[1][7] = fmaf(x1, whi.w, acc[1][7]);
    }

    #pragma unroll
    for (int i = 0; i < 2; i++) {
        int row = row_base + r0 + i;
        if (row < N_NODES) {
            float4 vlo, vhi;
            vlo.x = leaky(acc[i][0]); vlo.y = leaky(acc[i][1]);
            vlo.z = leaky(acc[i][2]); vlo.w = leaky(acc[i][3]);
            vhi.x = leaky(acc[i][4]); vhi.y = leaky(acc[i][5]);
            vhi.z = leaky(acc[i][6]); vhi.w = leaky(acc[i][7]);
            *(float4*)(out + (long long)row * D + c0)     = vlo;
            *(float4*)(out + (long long)row * D + c0 + 4) = vhi;
        }
    }
}

// ---------------------------------------------------------------------------
// launch
// ---------------------------------------------------------------------------
extern "C" void kernel_launch(void* const* d_in, const int* in_sizes, int n_in,
                              void* d_out, int out_size) {
    const float* x   = (const float*)d_in[0];
    const int*   ei  = (const int*)d_in[1];      // int32 (JAX downcasts int64)
    const float* eps = (const float*)d_in[2];
    const float* W1  = (const float*)d_in[3];
    const float* b1  = (const float*)d_in[4];
    const float* W2  = (const float*)d_in[5];
    const float* b2  = (const float*)d_in[6];
    float* out = (float*)d_out;

    float* agg;  cudaGetSymbolAddress((void**)&agg,  g_agg);
    int*   cnt;  cudaGetSymbolAddress((void**)&cnt,  g_count);
    int*   off;  cudaGetSymbolAddress((void**)&off,  g_off);
    int*   csrs; cudaGetSymbolAddress((void**)&csrs, g_src);

    zero_kernel<<<(N_NODES + 255) / 256, 256>>>(cnt);
    hist_kernel<<<(N_EDGES + 255) / 256, 256>>>(ei, cnt);
    scan_kernel<<<1, SCAN_T>>>(cnt, off);
    fill_kernel<<<(N_EDGES + 255) / 256, 256>>>(ei, off, cnt, csrs);

    {
        // one warp per node, 8 warps per block
        int blocks = (N_NODES + 7) / 8;
        gather_kernel<<<blocks, 256>>>((const float2*)x, eps, off, csrs,
                                       (float2*)agg);
    }
    {
        int blocks = (N_NODES + MLP_ROWS - 1) / MLP_ROWS;
        mlp_kernel<<<blocks, 256>>>(agg, W1, b1, W2, b2, out);
    }
}

// round 4
// speedup vs baseline: 1.8219x; 1.8219x over previous
#include <cuda_runtime.h>
#include <cuda_bf16.h>
#include <cstdint>

#define N_NODES 100000
#define N_EDGES 1000000
#define D 64

#define SCAN_BLK 256
#define N_SBLKS ((N_NODES + SCAN_BLK - 1) / SCAN_BLK)   // 391

// ---------------------------------------------------------------------------
// Scratch (__device__ globals; no allocation allowed)
// ---------------------------------------------------------------------------
__device__ float g_agg[N_NODES * D];
__device__ int   g_count[N_NODES];        // degree histogram -> cursors
__device__ int   g_off[N_NODES + 1];      // CSR offsets
__device__ int   g_src[N_EDGES];          // CSR src lists (grouped by dst)
__device__ int   g_bsum[N_SBLKS + 1];     // per-block sums / prefixes

// ---------------------------------------------------------------------------
// K1: zero counts (vectorized)
// ---------------------------------------------------------------------------
__global__ void zero_kernel(int4* __restrict__ cnt4) {
    int i = blockIdx.x * blockDim.x + threadIdx.x;
    if (i < N_NODES / 4) cnt4[i] = make_int4(0, 0, 0, 0);
}

// ---------------------------------------------------------------------------
// K2: histogram of dst
// ---------------------------------------------------------------------------
__global__ void hist_kernel(const int* __restrict__ ei, int* __restrict__ cnt) {
    int e = blockIdx.x * blockDim.x + threadIdx.x;
    if (e < N_EDGES) {
        int dst = ei[N_EDGES + e];
        if ((unsigned)dst < N_NODES) atomicAdd(&cnt[dst], 1);
    }
}

// ---------------------------------------------------------------------------
// K3a: per-block reduction of counts (coalesced)
// ---------------------------------------------------------------------------
__global__ __launch_bounds__(SCAN_BLK)
void scan_reduce_kernel(const int* __restrict__ cnt, int* __restrict__ bsum) {
    __shared__ int sm[SCAN_BLK];
    int i = blockIdx.x * SCAN_BLK + threadIdx.x;
    int v = (i < N_NODES) ? cnt[i] : 0;
    sm[threadIdx.x] = v;
    __syncthreads();
    for (int s = SCAN_BLK / 2; s > 0; s >>= 1) {
        if (threadIdx.x < s) sm[threadIdx.x] += sm[threadIdx.x + s];
        __syncthreads();
    }
    if (threadIdx.x == 0) bsum[blockIdx.x] = sm[0];
}

// ---------------------------------------------------------------------------
// K3b: exclusive scan of block sums (1 block, 512 threads >= 391)
// ---------------------------------------------------------------------------
__global__ __launch_bounds__(512)
void scan_bsum_kernel(int* __restrict__ bsum) {
    __shared__ int sm[512];
    int t = threadIdx.x;
    int v = (t < N_SBLKS) ? bsum[t] : 0;
    sm[t] = v;
    for (int ofs = 1; ofs < 512; ofs <<= 1) {
        __syncthreads();
        int u = (t >= ofs) ? sm[t - ofs] : 0;
        __syncthreads();
        sm[t] += u;
    }
    __syncthreads();
    if (t < N_SBLKS) bsum[t] = sm[t] - v;            // exclusive
    if (t == 0) bsum[N_SBLKS] = sm[511];             // total (== valid edges)
}

// ---------------------------------------------------------------------------
// K3c: block-local exclusive scan + block prefix -> offsets; zero counts.
// ---------------------------------------------------------------------------
__global__ __launch_bounds__(SCAN_BLK)
void scan_offsets_kernel(int* __restrict__ cnt, const int* __restrict__ bsum,
                         int* __restrict__ off) {
    __shared__ int sm[SCAN_BLK];
    int i = blockIdx.x * SCAN_BLK + threadIdx.x;
    int t = threadIdx.x;
    int v = (i < N_NODES) ? cnt[i] : 0;
    sm[t] = v;
    for (int ofs = 1; ofs < SCAN_BLK; ofs <<= 1) {
        __syncthreads();
        int u = (t >= ofs) ? sm[t - ofs] : 0;
        __syncthreads();
        sm[t] += u;
    }
    __syncthreads();
    if (i < N_NODES) {
        off[i] = bsum[blockIdx.x] + sm[t] - v;       // exclusive prefix
        cnt[i] = 0;                                  // reset cursor
    }
    if (i == N_NODES - 1 || (blockIdx.x == N_SBLKS - 1 && t == SCAN_BLK - 1))
        off[N_NODES] = bsum[N_SBLKS];
}

// ---------------------------------------------------------------------------
// K4: fill CSR src lists
// ---------------------------------------------------------------------------
__global__ void fill_kernel(const int* __restrict__ ei,
                            const int* __restrict__ off,
                            int* __restrict__ cur,
                            int* __restrict__ csr_src) {
    int e = blockIdx.x * blockDim.x + threadIdx.x;
    if (e < N_EDGES) {
        int src = ei[e];
        int dst = ei[N_EDGES + e];
        if ((unsigned)src >= N_NODES || (unsigned)dst >= N_NODES) return;
        int pos = off[dst] + atomicAdd(&cur[dst], 1);
        csr_src[pos] = src;
    }
}

// ---------------------------------------------------------------------------
// K5: gather + fused (1+eps)*x. One warp per node; lane owns a float2.
// Unroll-by-4: 4 independent 256B row loads in flight per lane.
// ---------------------------------------------------------------------------
__global__ __launch_bounds__(256)
void gather_kernel(const float2* __restrict__ x2,
                   const float* __restrict__ eps,
                   const int* __restrict__ off,
                   const int* __restrict__ csr_src,
                   float2* __restrict__ agg2) {
    int warp = (blockIdx.x * blockDim.x + threadIdx.x) >> 5;
    int lane = threadIdx.x & 31;
    if (warp >= N_NODES) return;

    float s = 1.0f + *eps;
    float2 v = x2[(long long)warp * 32 + lane];
    float ax = s * v.x, ay = s * v.y;

    int k   = off[warp];
    int end = off[warp + 1];

    for (; k + 4 <= end; k += 4) {
        int s0 = csr_src[k];
        int s1 = csr_src[k + 1];
        int s2 = csr_src[k + 2];
        int s3 = csr_src[k + 3];
        float2 n0 = x2[(long long)s0 * 32 + lane];
        float2 n1 = x2[(long long)s1 * 32 + lane];
        float2 n2 = x2[(long long)s2 * 32 + lane];
        float2 n3 = x2[(long long)s3 * 32 + lane];
        ax += (n0.x + n1.x) + (n2.x + n3.x);
        ay += (n0.y + n1.y) + (n2.y + n3.y);
    }
    for (; k < end; k++) {
        int s0 = csr_src[k];
        float2 n0 = x2[(long long)s0 * 32 + lane];
        ax += n0.x;
        ay += n0.y;
    }
    float2 o; o.x = ax; o.y = ay;
    agg2[(long long)warp * 32 + lane] = o;
}

// ---------------------------------------------------------------------------
// K6: fused 2-layer MLP with LeakyReLU.
// ---------------------------------------------------------------------------
#define MLP_ROWS 64
#define XS_STRIDE 66

__device__ __forceinline__ float leaky(float v) {
    return fmaxf(v, 0.01f * v);
}

__global__ __launch_bounds__(256, 2)
void mlp_kernel(const float* __restrict__ agg,
                const float* __restrict__ W1, const float* __restrict__ b1,
                const float* __restrict__ W2, const float* __restrict__ b2,
                float* __restrict__ out) {
    __shared__ float Xs[MLP_ROWS][XS_STRIDE];
    __shared__ float Ws[D][D];
    __shared__ float bs[D];

    const int tid = threadIdx.x;
    const int cg  = tid & 7;
    const int rg  = tid >> 3;
    const int row_base = blockIdx.x * MLP_ROWS;

    {
        const float2* src = (const float2*)(agg + (long long)row_base * D);
        for (int idx = tid; idx < MLP_ROWS * (D / 2); idx += 256) {
            int r = idx >> 5;
            int p = idx & 31;
            float2 v;
            if (row_base + r < N_NODES) v = src[r * 32 + p];
            else { v.x = 0.f; v.y = 0.f; }
            Xs[r][p * 2]     = v.x;
            Xs[r][p * 2 + 1] = v.y;
        }
    }
    {
        const float4* w = (const float4*)W1;
        float4* ws = (float4*)&Ws[0][0];
        for (int idx = tid; idx < D * D / 4; idx += 256) ws[idx] = w[idx];
        if (tid < D) bs[tid] = b1[tid];
    }
    __syncthreads();

    const int r0 = rg * 2;
    const int c0 = cg * 8;

    float acc[2][8];
    #pragma unroll
    for (int j = 0; j < 8; j++) { acc[0][j] = bs[c0 + j]; acc[1][j] = bs[c0 + j]; }

    #pragma unroll 8
    for (int k = 0; k < D; k++) {
        float x0 = Xs[r0][k];
        float x1 = Xs[r0 + 1][k];
        float4 wlo = *(const float4*)&Ws[k][c0];
        float4 whi = *(const float4*)&Ws[k][c0 + 4];
        acc[0][0] = fmaf(x0, wlo.x, acc[0][0]); acc[1][0] = fmaf(x1, wlo.x, acc[1][0]);
        acc[0][1] = fmaf(x0, wlo.y, acc[0][1]); acc[1][1] = fmaf(x1, wlo.y, acc[1][1]);
        acc[0][2] = fmaf(x0, wlo.z, acc[0][2]); acc[1][2] = fmaf(x1, wlo.z, acc[1][2]);
        acc[0][3] = fmaf(x0, wlo.w, acc[0][3]); acc[1][3] = fmaf(x1, wlo.w, acc[1][3]);
        acc[0][4] = fmaf(x0, whi.x, acc[0][4]); acc[1][4] = fmaf(x1, whi.x, acc[1][4]);
        acc[0][5] = fmaf(x0, whi.y, acc[0][5]); acc[1][5] = fmaf(x1, whi.y, acc[1][5]);
        acc[0][6] = fmaf(x0, whi.z, acc[0][6]); acc[1][6] = fmaf(x1, whi.z, acc[1][6]);
        acc[0][7] = fmaf(x0, whi.w, acc[0][7]); acc[1][7] = fmaf(x1, whi.w, acc[1][7]);
    }
    __syncthreads();

    #pragma unroll
    for (int i = 0; i < 2; i++)
        #pragma unroll
        for (int j = 0; j < 8; j++)
            Xs[r0 + i][c0 + j] = leaky(acc[i][j]);

    {
        const float4* w = (const float4*)W2;
        float4* ws = (float4*)&Ws[0][0];
        for (int idx = tid; idx < D * D / 4; idx += 256) ws[idx] = w[idx];
        if (tid < D) bs[tid] = b2[tid];
    }
    __syncthreads();

    #pragma unroll
    for (int j = 0; j < 8; j++) { acc[0][j] = bs[c0 + j]; acc[1][j] = bs[c0 + j]; }

    #pragma unroll 8
    for (int k = 0; k < D; k++) {
        float x0 = Xs[r0][k];
        float x1 = Xs[r0 + 1][k];
        float4 wlo = *(const float4*)&Ws[k][c0];
        float4 whi = *(const float4*)&Ws[k][c0 + 4];
        acc[0][0] = fmaf(x0, wlo.x, acc[0][0]); acc[1][0] = fmaf(x1, wlo.x, acc[1][0]);
        acc[0][1] = fmaf(x0, wlo.y, acc[0][1]); acc[1][1] = fmaf(x1, wlo.y, acc[1][1]);
        acc[0][2] = fmaf(x0, wlo.z, acc[0][2]); acc[1][2] = fmaf(x1, wlo.z, acc[1][2]);
        acc[0][3] = fmaf(x0, wlo.w, acc[0][3]); acc[1][3] = fmaf(x1, wlo.w, acc[1][3]);
        acc[0][4] = fmaf(x0, whi.x, acc[0][4]); acc[1][4] = fmaf(x1, whi.x, acc[1][4]);
        acc[0][5] = fmaf(x0, whi.y, acc[0][5]); acc[1][5] = fmaf(x1, whi.y, acc[1][5]);
        acc[0][6] = fmaf(x0, whi.z, acc[0][6]); acc[1][6] = fmaf(x1, whi.z, acc[1][6]);
        acc[0][7] = fmaf(x0, whi.w, acc[0][7]); acc[1][7] = fmaf(x1, whi.w, acc[1][7]);
    }

    #pragma unroll
    for (int i = 0; i < 2; i++) {
        int row = row_base + r0 + i;
        if (row < N_NODES) {
            float4 vlo, vhi;
            vlo.x = leaky(acc[i][0]); vlo.y = leaky(acc[i][1]);
            vlo.z = leaky(acc[i][2]); vlo.w = leaky(acc[i][3]);
            vhi.x = leaky(acc[i][4]); vhi.y = leaky(acc[i][5]);
            vhi.z = leaky(acc[i][6]); vhi.w = leaky(acc[i][7]);
            *(float4*)(out + (long long)row * D + c0)     = vlo;
            *(float4*)(out + (long long)row * D + c0 + 4) = vhi;
        }
    }
}

// ---------------------------------------------------------------------------
// launch
// ---------------------------------------------------------------------------
extern "C" void kernel_launch(void* const* d_in, const int* in_sizes, int n_in,
                              void* d_out, int out_size) {
    const float* x   = (const float*)d_in[0];
    const int*   ei  = (const int*)d_in[1];      // int32 (JAX downcasts int64)
    const float* eps = (const float*)d_in[2];
    const float* W1  = (const float*)d_in[3];
    const float* b1  = (const float*)d_in[4];
    const float* W2  = (const float*)d_in[5];
    const float* b2  = (const float*)d_in[6];
    float* out = (float*)d_out;

    float* agg;  cudaGetSymbolAddress((void**)&agg,  g_agg);
    int*   cnt;  cudaGetSymbolAddress((void**)&cnt,  g_count);
    int*   off;  cudaGetSymbolAddress((void**)&off,  g_off);
    int*   csrs; cudaGetSymbolAddress((void**)&csrs, g_src);
    int*   bsum; cudaGetSymbolAddress((void**)&bsum, g_bsum);

    zero_kernel<<<(N_NODES / 4 + 255) / 256, 256>>>((int4*)cnt);
    hist_kernel<<<(N_EDGES + 255) / 256, 256>>>(ei, cnt);
    scan_reduce_kernel<<<N_SBLKS, SCAN_BLK>>>(cnt, bsum);
    scan_bsum_kernel<<<1, 512>>>(bsum);
    scan_offsets_kernel<<<N_SBLKS, SCAN_BLK>>>(cnt, bsum, off);
    fill_kernel<<<(N_EDGES + 255) / 256, 256>>>(ei, off, cnt, csrs);

    {
        int blocks = (N_NODES + 7) / 8;   // one warp per node, 8 warps/block
        gather_kernel<<<blocks, 256>>>((const float2*)x, eps, off, csrs,
                                       (float2*)agg);
    }
    {
        int blocks = (N_NODES + MLP_ROWS - 1) / MLP_ROWS;
        mlp_kernel<<<blocks, 256>>>(agg, W1, b1, W2, b2, out);
    }
}

// round 5
// speedup vs baseline: 1.8678x; 1.0252x over previous
#include <cuda_runtime.h>
#include <cuda_bf16.h>
#include <cstdint>

#define N_NODES 100000
#define N_EDGES 1000000
#define D 64

typedef unsigned long long u64;

// ---------------------------------------------------------------------------
// Scratch (__device__ globals; no allocation allowed)
// ---------------------------------------------------------------------------
__device__ float g_agg[N_NODES * D];
__device__ int   g_count[N_NODES];        // degree histogram -> cursors
__device__ int   g_off[N_NODES];          // CSR segment starts
__device__ int   g_end[N_NODES];          // CSR segment ends
__device__ int   g_src[N_EDGES];          // CSR src lists (grouped by dst)
__device__ int   g_base;                  // atomic base for block offsets

// ---------------------------------------------------------------------------
// K1: zero counts + base
// ---------------------------------------------------------------------------
__global__ void zero_kernel(int4* __restrict__ cnt4, int* __restrict__ base) {
    int i = blockIdx.x * blockDim.x + threadIdx.x;
    if (i < N_NODES / 4) cnt4[i] = make_int4(0, 0, 0, 0);
    if (i == 0) *base = 0;
}

// ---------------------------------------------------------------------------
// K2: histogram of dst
// ---------------------------------------------------------------------------
__global__ void hist_kernel(const int* __restrict__ ei, int* __restrict__ cnt) {
    int e = blockIdx.x * blockDim.x + threadIdx.x;
    if (e < N_EDGES) {
        int dst = ei[N_EDGES + e];
        if ((unsigned)dst < N_NODES) atomicAdd(&cnt[dst], 1);
    }
}

// ---------------------------------------------------------------------------
// K3: one-kernel offsets: block scan + atomic base. Segments stay contiguous
// per node; global layout order is irrelevant for a commutative sum.
// ---------------------------------------------------------------------------
#define SCAN_BLK 256
#define N_SBLKS ((N_NODES + SCAN_BLK - 1) / SCAN_BLK)   // 391

__global__ __launch_bounds__(SCAN_BLK)
void scan_atomic_kernel(int* __restrict__ cnt, int* __restrict__ off,
                        int* __restrict__ endp, int* __restrict__ base) {
    __shared__ int sm[SCAN_BLK];
    __shared__ int sbase;
    int i = blockIdx.x * SCAN_BLK + threadIdx.x;
    int t = threadIdx.x;
    int v = (i < N_NODES) ? cnt[i] : 0;
    sm[t] = v;
    for (int ofs = 1; ofs < SCAN_BLK; ofs <<= 1) {
        __syncthreads();
        int u = (t >= ofs) ? sm[t - ofs] : 0;
        __syncthreads();
        sm[t] += u;
    }
    __syncthreads();
    if (t == SCAN_BLK - 1) sbase = atomicAdd(base, sm[SCAN_BLK - 1]);
    __syncthreads();
    if (i < N_NODES) {
        int incl = sbase + sm[t];
        off[i]  = incl - v;
        endp[i] = incl;
        cnt[i]  = 0;                      // reset cursor for fill
    }
}

// ---------------------------------------------------------------------------
// K4: fill CSR src lists
// ---------------------------------------------------------------------------
__global__ void fill_kernel(const int* __restrict__ ei,
                            const int* __restrict__ off,
                            int* __restrict__ cur,
                            int* __restrict__ csr_src) {
    int e = blockIdx.x * blockDim.x + threadIdx.x;
    if (e < N_EDGES) {
        int src = ei[e];
        int dst = ei[N_EDGES + e];
        if ((unsigned)src >= N_NODES || (unsigned)dst >= N_NODES) return;
        int pos = off[dst] + atomicAdd(&cur[dst], 1);
        csr_src[pos] = src;
    }
}

// ---------------------------------------------------------------------------
// K5: gather + fused (1+eps)*x. One warp per node; lane owns a float2.
// Unroll-8 batches: 8 independent 256B row loads in flight. 32-bit indexing.
// ---------------------------------------------------------------------------
__global__ __launch_bounds__(256)
void gather_kernel(const float2* __restrict__ x2,
                   const float* __restrict__ eps,
                   const int* __restrict__ off,
                   const int* __restrict__ endp,
                   const int* __restrict__ csr_src,
                   float2* __restrict__ agg2) {
    int warp = (blockIdx.x * blockDim.x + threadIdx.x) >> 5;
    int lane = threadIdx.x & 31;
    if (warp >= N_NODES) return;

    float s = 1.0f + *eps;
    unsigned self = (unsigned)warp * 32u + (unsigned)lane;
    float2 v = x2[self];
    float ax = s * v.x, ay = s * v.y;

    int k   = off[warp];
    int end = endp[warp];

    for (; k + 8 <= end; k += 8) {
        unsigned idx[8];
        #pragma unroll
        for (int u = 0; u < 8; u++)
            idx[u] = (unsigned)csr_src[k + u] * 32u + (unsigned)lane;
        #pragma unroll
        for (int u = 0; u < 8; u++) {
            float2 n = x2[idx[u]];
            ax += n.x; ay += n.y;
        }
    }
    if (k + 4 <= end) {
        unsigned i0 = (unsigned)csr_src[k]     * 32u + lane;
        unsigned i1 = (unsigned)csr_src[k + 1] * 32u + lane;
        unsigned i2 = (unsigned)csr_src[k + 2] * 32u + lane;
        unsigned i3 = (unsigned)csr_src[k + 3] * 32u + lane;
        float2 n0 = x2[i0], n1 = x2[i1], n2 = x2[i2], n3 = x2[i3];
        ax += (n0.x + n1.x) + (n2.x + n3.x);
        ay += (n0.y + n1.y) + (n2.y + n3.y);
        k += 4;
    }
    for (; k < end; k++) {
        float2 n = x2[(unsigned)csr_src[k] * 32u + lane];
        ax += n.x; ay += n.y;
    }
    float2 o; o.x = ax; o.y = ay;
    agg2[self] = o;
}

// ---------------------------------------------------------------------------
// K6: fused 2-layer MLP with LeakyReLU, packed fma.rn.f32x2.
// Each thread: 2 rows x 8 cols = 2x4 packed f32x2 accumulators.
// Weight pairs come out of smem as ulonglong2 (LDS.128 -> 2 packed operands).
// ---------------------------------------------------------------------------
#define MLP_ROWS 64
#define XS_STRIDE 66

__device__ __forceinline__ float leaky(float v) {
    return fmaxf(v, 0.01f * v);
}

#define FMA2(d, a, b, c) \
    asm("fma.rn.f32x2 %0, %1, %2, %3;" : "=l"(d) : "l"(a), "l"(b), "l"(c))
#define PACK_DUP(out, f) \
    asm("mov.b64 %0, {%1, %1};" : "=l"(out) : "r"(__float_as_uint(f)))
#define PACK2F(out, lo, hi) \
    asm("mov.b64 %0, {%1, %2};" : "=l"(out) : "r"(__float_as_uint(lo)), "r"(__float_as_uint(hi)))
#define UNPACK2F(lo, hi, in) \
    { unsigned _l, _h; asm("mov.b64 {%0, %1}, %2;" : "=r"(_l), "=r"(_h) : "l"(in)); \
      lo = __uint_as_float(_l); hi = __uint_as_float(_h); }

__global__ __launch_bounds__(256, 2)
void mlp_kernel(const float* __restrict__ agg,
                const float* __restrict__ W1, const float* __restrict__ b1,
                const float* __restrict__ W2, const float* __restrict__ b2,
                float* __restrict__ out) {
    __shared__ float Xs[MLP_ROWS][XS_STRIDE];
    __shared__ float Ws[D][D];
    __shared__ float bs[D];

    const int tid = threadIdx.x;
    const int cg  = tid & 7;
    const int rg  = tid >> 3;
    const int row_base = blockIdx.x * MLP_ROWS;
    const int r0 = rg * 2;
    const int c0 = cg * 8;

    {
        const float2* src = (const float2*)(agg + (long long)row_base * D);
        for (int idx = tid; idx < MLP_ROWS * (D / 2); idx += 256) {
            int r = idx >> 5;
            int p = idx & 31;
            float2 v;
            if (row_base + r < N_NODES) v = src[r * 32 + p];
            else { v.x = 0.f; v.y = 0.f; }
            Xs[r][p * 2]     = v.x;
            Xs[r][p * 2 + 1] = v.y;
        }
    }
    {
        const float4* w = (const float4*)W1;
        float4* ws = (float4*)&Ws[0][0];
        for (int idx = tid; idx < D * D / 4; idx += 256) ws[idx] = w[idx];
        if (tid < D) bs[tid] = b1[tid];
    }
    __syncthreads();

    // ---------------- layer 1 ----------------
    u64 acc[2][4];
    #pragma unroll
    for (int j = 0; j < 4; j++) {
        u64 bp; PACK2F(bp, bs[c0 + 2 * j], bs[c0 + 2 * j + 1]);
        acc[0][j] = bp; acc[1][j] = bp;
    }

    #pragma unroll 8
    for (int k = 0; k < D; k++) {
        u64 xx0, xx1;
        PACK_DUP(xx0, Xs[r0][k]);
        PACK_DUP(xx1, Xs[r0 + 1][k]);
        ulonglong2 wa = *(const ulonglong2*)&Ws[k][c0];       // {w0w1, w2w3}
        ulonglong2 wb = *(const ulonglong2*)&Ws[k][c0 + 4];   // {w4w5, w6w7}
        FMA2(acc[0][0], xx0, wa.x, acc[0][0]); FMA2(acc[1][0], xx1, wa.x, acc[1][0]);
        FMA2(acc[0][1], xx0, wa.y, acc[0][1]); FMA2(acc[1][1], xx1, wa.y, acc[1][1]);
        FMA2(acc[0][2], xx0, wb.x, acc[0][2]); FMA2(acc[1][2], xx1, wb.x, acc[1][2]);
        FMA2(acc[0][3], xx0, wb.y, acc[0][3]); FMA2(acc[1][3], xx1, wb.y, acc[1][3]);
    }
    __syncthreads();

    // leaky + write back into Xs
    #pragma unroll
    for (int i = 0; i < 2; i++)
        #pragma unroll
        for (int j = 0; j < 4; j++) {
            float lo, hi; UNPACK2F(lo, hi, acc[i][j]);
            Xs[r0 + i][c0 + 2 * j]     = leaky(lo);
            Xs[r0 + i][c0 + 2 * j + 1] = leaky(hi);
        }

    {
        const float4* w = (const float4*)W2;
        float4* ws = (float4*)&Ws[0][0];
        for (int idx = tid; idx < D * D / 4; idx += 256) ws[idx] = w[idx];
        if (tid < D) bs[tid] = b2[tid];
    }
    __syncthreads();

    // ---------------- layer 2 ----------------
    #pragma unroll
    for (int j = 0; j < 4; j++) {
        u64 bp; PACK2F(bp, bs[c0 + 2 * j], bs[c0 + 2 * j + 1]);
        acc[0][j] = bp; acc[1][j] = bp;
    }

    #pragma unroll 8
    for (int k = 0; k < D; k++) {
        u64 xx0, xx1;
        PACK_DUP(xx0, Xs[r0][k]);
        PACK_DUP(xx1, Xs[r0 + 1][k]);
        ulonglong2 wa = *(const ulonglong2*)&Ws[k][c0];
        ulonglong2 wb = *(const ulonglong2*)&Ws[k][c0 + 4];
        FMA2(acc[0][0], xx0, wa.x, acc[0][0]); FMA2(acc[1][0], xx1, wa.x, acc[1][0]);
        FMA2(acc[0][1], xx0, wa.y, acc[0][1]); FMA2(acc[1][1], xx1, wa.y, acc[1][1]);
        FMA2(acc[0][2], xx0, wb.x, acc[0][2]); FMA2(acc[1][2], xx1, wb.x, acc[1][2]);
        FMA2(acc[0][3], xx0, wb.y, acc[0][3]); FMA2(acc[1][3], xx1, wb.y, acc[1][3]);
    }

    // --- store output ---
    #pragma unroll
    for (int i = 0; i < 2; i++) {
        int row = row_base + r0 + i;
        if (row < N_NODES) {
            float4 vlo, vhi;
            float lo, hi;
            UNPACK2F(lo, hi, acc[i][0]); vlo.x = leaky(lo); vlo.y = leaky(hi);
            UNPACK2F(lo, hi, acc[i][1]); vlo.z = leaky(lo); vlo.w = leaky(hi);
            UNPACK2F(lo, hi, acc[i][2]); vhi.x = leaky(lo); vhi.y = leaky(hi);
            UNPACK2F(lo, hi, acc[i][3]); vhi.z = leaky(lo); vhi.w = leaky(hi);
            *(float4*)(out + (long long)row * D + c0)     = vlo;
            *(float4*)(out + (long long)row * D + c0 + 4) = vhi;
        }
    }
}

// ---------------------------------------------------------------------------
// launch
// ---------------------------------------------------------------------------
extern "C" void kernel_launch(void* const* d_in, const int* in_sizes, int n_in,
                              void* d_out, int out_size) {
    const float* x   = (const float*)d_in[0];
    const int*   ei  = (const int*)d_in[1];      // int32 (JAX downcasts int64)
    const float* eps = (const float*)d_in[2];
    const float* W1  = (const float*)d_in[3];
    const float* b1  = (const float*)d_in[4];
    const float* W2  = (const float*)d_in[5];
    const float* b2  = (const float*)d_in[6];
    float* out = (float*)d_out;

    float* agg;  cudaGetSymbolAddress((void**)&agg,  g_agg);
    int*   cnt;  cudaGetSymbolAddress((void**)&cnt,  g_count);
    int*   off;  cudaGetSymbolAddress((void**)&off,  g_off);
    int*   endp; cudaGetSymbolAddress((void**)&endp, g_end);
    int*   csrs; cudaGetSymbolAddress((void**)&csrs, g_src);
    int*   base; cudaGetSymbolAddress((void**)&base, g_base);

    zero_kernel<<<(N_NODES / 4 + 255) / 256, 256>>>((int4*)cnt, base);
    hist_kernel<<<(N_EDGES + 255) / 256, 256>>>(ei, cnt);
    scan_atomic_kernel<<<N_SBLKS, SCAN_BLK>>>(cnt, off, endp, base);
    fill_kernel<<<(N_EDGES + 255) / 256, 256>>>(ei, off, cnt, csrs);

    {
        int blocks = (N_NODES + 7) / 8;   // one warp per node, 8 warps/block
        gather_kernel<<<blocks, 256>>>((const float2*)x, eps, off, endp, csrs,
                                       (float2*)agg);
    }
    {
        int blocks = (N_NODES + MLP_ROWS - 1) / MLP_ROWS;
        mlp_kernel<<<blocks, 256>>>(agg, W1, b1, W2, b2, out);
    }
}

// round 6
// speedup vs baseline: 1.9136x; 1.0245x over previous
#include <cuda_runtime.h>
#include <cuda_bf16.h>
#include <cstdint>

#define N_NODES 100000
#define N_EDGES 1000000
#define D 64

typedef unsigned long long u64;

// ---------------------------------------------------------------------------
// Scratch. NOTE: g_count starts zero (device globals are zero-initialized)
// and every kernel_launch leaves it zero (scan resets it) -> no zero kernel.
// ---------------------------------------------------------------------------
__device__ float g_agg[N_NODES * D];
__device__ int   g_count[N_NODES];        // degree histogram (invariant: 0 between calls)
__device__ int   g_off[N_NODES];          // CSR segment starts
__device__ int   g_end[N_NODES];          // CSR segment ends
__device__ int   g_cur[N_NODES];          // fill cursors (consumed)
__device__ int   g_src[N_EDGES];          // CSR src lists (grouped by dst)
__device__ int   g_base;                  // atomic base for block offsets

// ---------------------------------------------------------------------------
// K0: histogram of dst  (launch #0)
// ---------------------------------------------------------------------------
__global__ void hist_kernel(const int* __restrict__ ei, int* __restrict__ cnt,
                            int* __restrict__ base) {
    int e = blockIdx.x * blockDim.x + threadIdx.x;
    if (e == 0) *base = 0;
    if (e < N_EDGES) {
        int dst = ei[N_EDGES + e];
        if ((unsigned)dst < N_NODES) atomicAdd(&cnt[dst], 1);
    }
}

// ---------------------------------------------------------------------------
// K1: block scan + atomic base -> off/end/cur; reset cnt to 0.  (launch #1)
// ---------------------------------------------------------------------------
#define SCAN_BLK 256
#define N_SBLKS ((N_NODES + SCAN_BLK - 1) / SCAN_BLK)   // 391

__global__ __launch_bounds__(SCAN_BLK)
void scan_atomic_kernel(int* __restrict__ cnt, int* __restrict__ off,
                        int* __restrict__ endp, int* __restrict__ cur,
                        int* __restrict__ base) {
    __shared__ int sm[SCAN_BLK];
    __shared__ int sbase;
    int i = blockIdx.x * SCAN_BLK + threadIdx.x;
    int t = threadIdx.x;
    int v = (i < N_NODES) ? cnt[i] : 0;
    sm[t] = v;
    for (int ofs = 1; ofs < SCAN_BLK; ofs <<= 1) {
        __syncthreads();
        int u = (t >= ofs) ? sm[t - ofs] : 0;
        __syncthreads();
        sm[t] += u;
    }
    __syncthreads();
    if (t == SCAN_BLK - 1) sbase = atomicAdd(base, sm[SCAN_BLK - 1]);
    __syncthreads();
    if (i < N_NODES) {
        int incl = sbase + sm[t];
        int st = incl - v;
        off[i]  = st;
        cur[i]  = st;
        endp[i] = incl;
        cnt[i]  = 0;                      // restore zero-invariant
    }
}

// ---------------------------------------------------------------------------
// K2: fill CSR src lists  (launch #2)
// ---------------------------------------------------------------------------
__global__ void fill_kernel(const int* __restrict__ ei,
                            int* __restrict__ cur,
                            int* __restrict__ csr_src) {
    int e = blockIdx.x * blockDim.x + threadIdx.x;
    if (e < N_EDGES) {
        int src = ei[e];
        int dst = ei[N_EDGES + e];
        if ((unsigned)src >= N_NODES || (unsigned)dst >= N_NODES) return;
        int pos = atomicAdd(&cur[dst], 1);
        csr_src[pos] = src;
    }
}

// ---------------------------------------------------------------------------
// K3: gather + fused (1+eps)*x.  (launch #3 -> gets profiled)
// One warp per node; lane owns a float2. Parallel index fetch (coalesced,
// lane L reads csr_src[base+L]) + shfl broadcast; row loads issued in
// predicated batches of 4 -> no serial csr->row dependent chain.
// ---------------------------------------------------------------------------
__global__ __launch_bounds__(256)
void gather_kernel(const float2* __restrict__ x2,
                   const float* __restrict__ eps,
                   const int* __restrict__ off,
                   const int* __restrict__ endp,
                   const int* __restrict__ csr_src,
                   float2* __restrict__ agg2) {
    int warp = (blockIdx.x * blockDim.x + threadIdx.x) >> 5;
    int lane = threadIdx.x & 31;
    if (warp >= N_NODES) return;

    float s = 1.0f + *eps;
    unsigned self = (unsigned)warp * 32u + (unsigned)lane;
    float2 v = x2[self];
    float ax = s * v.x, ay = s * v.y;

    int start = off[warp];
    int end   = endp[warp];

    for (int base = start; base < end; base += 32) {
        int n = min(32, end - base);
        int myidx = (lane < n) ? csr_src[base + lane] : 0;
        for (int j = 0; j < n; j += 4) {
            int s0 = __shfl_sync(0xffffffffu, myidx, j);
            int s1 = __shfl_sync(0xffffffffu, myidx, j + 1);
            int s2 = __shfl_sync(0xffffffffu, myidx, j + 2);
            int s3 = __shfl_sync(0xffffffffu, myidx, j + 3);
            float2 n0 = x2[(unsigned)s0 * 32u + lane];
            float2 n1 = x2[(unsigned)s1 * 32u + lane];
            float2 n2 = x2[(unsigned)s2 * 32u + lane];
            float2 n3 = x2[(unsigned)s3 * 32u + lane];
            ax += n0.x; ay += n0.y;
            if (j + 1 < n) { ax += n1.x; ay += n1.y; }
            if (j + 2 < n) { ax += n2.x; ay += n2.y; }
            if (j + 3 < n) { ax += n3.x; ay += n3.y; }
        }
    }
    float2 o; o.x = ax; o.y = ay;
    agg2[self] = o;
}

// ---------------------------------------------------------------------------
// K4: fused 2-layer MLP with LeakyReLU, packed fma.rn.f32x2.  (launch #4)
// ---------------------------------------------------------------------------
#define MLP_ROWS 64
#define XS_STRIDE 66

__device__ __forceinline__ float leaky(float v) {
    return fmaxf(v, 0.01f * v);
}

#define FMA2(d, a, b, c) \
    asm("fma.rn.f32x2 %0, %1, %2, %3;" : "=l"(d) : "l"(a), "l"(b), "l"(c))
#define PACK_DUP(out, f) \
    asm("mov.b64 %0, {%1, %1};" : "=l"(out) : "r"(__float_as_uint(f)))
#define PACK2F(out, lo, hi) \
    asm("mov.b64 %0, {%1, %2};" : "=l"(out) : "r"(__float_as_uint(lo)), "r"(__float_as_uint(hi)))
#define UNPACK2F(lo, hi, in) \
    { unsigned _l, _h; asm("mov.b64 {%0, %1}, %2;" : "=r"(_l), "=r"(_h) : "l"(in)); \
      lo = __uint_as_float(_l); hi = __uint_as_float(_h); }

__global__ __launch_bounds__(256)
void mlp_kernel(const float* __restrict__ agg,
                const float* __restrict__ W1, const float* __restrict__ b1,
                const float* __restrict__ W2, const float* __restrict__ b2,
                float* __restrict__ out) {
    __shared__ float Xs[MLP_ROWS][XS_STRIDE];
    __shared__ float Ws[D][D];
    __shared__ float bs[D];

    const int tid = threadIdx.x;
    const int cg  = tid & 7;
    const int rg  = tid >> 3;
    const int row_base = blockIdx.x * MLP_ROWS;
    const int r0 = rg * 2;
    const int c0 = cg * 8;

    {
        const float2* src = (const float2*)(agg + (long long)row_base * D);
        for (int idx = tid; idx < MLP_ROWS * (D / 2); idx += 256) {
            int r = idx >> 5;
            int p = idx & 31;
            float2 v;
            if (row_base + r < N_NODES) v = src[r * 32 + p];
            else { v.x = 0.f; v.y = 0.f; }
            Xs[r][p * 2]     = v.x;
            Xs[r][p * 2 + 1] = v.y;
        }
    }
    {
        const float4* w = (const float4*)W1;
        float4* ws = (float4*)&Ws[0][0];
        for (int idx = tid; idx < D * D / 4; idx += 256) ws[idx] = w[idx];
        if (tid < D) bs[tid] = b1[tid];
    }
    __syncthreads();

    // ---------------- layer 1 ----------------
    u64 acc[2][4];
    #pragma unroll
    for (int j = 0; j < 4; j++) {
        u64 bp; PACK2F(bp, bs[c0 + 2 * j], bs[c0 + 2 * j + 1]);
        acc[0][j] = bp; acc[1][j] = bp;
    }

    #pragma unroll 8
    for (int k = 0; k < D; k++) {
        u64 xx0, xx1;
        PACK_DUP(xx0, Xs[r0][k]);
        PACK_DUP(xx1, Xs[r0 + 1][k]);
        ulonglong2 wa = *(const ulonglong2*)&Ws[k][c0];
        ulonglong2 wb = *(const ulonglong2*)&Ws[k][c0 + 4];
        FMA2(acc[0][0], xx0, wa.x, acc[0][0]); FMA2(acc[1][0], xx1, wa.x, acc[1][0]);
        FMA2(acc[0][1], xx0, wa.y, acc[0][1]); FMA2(acc[1][1], xx1, wa.y, acc[1][1]);
        FMA2(acc[0][2], xx0, wb.x, acc[0][2]); FMA2(acc[1][2], xx1, wb.x, acc[1][2]);
        FMA2(acc[0][3], xx0, wb.y, acc[0][3]); FMA2(acc[1][3], xx1, wb.y, acc[1][3]);
    }
    __syncthreads();

    #pragma unroll
    for (int i = 0; i < 2; i++)
        #pragma unroll
        for (int j = 0; j < 4; j++) {
            float lo, hi; UNPACK2F(lo, hi, acc[i][j]);
            Xs[r0 + i][c0 + 2 * j]     = leaky(lo);
            Xs[r0 + i][c0 + 2 * j + 1] = leaky(hi);
        }

    {
        const float4* w = (const float4*)W2;
        float4* ws = (float4*)&Ws[0][0];
        for (int idx = tid; idx < D * D / 4; idx += 256) ws[idx] = w[idx];
        if (tid < D) bs[tid] = b2[tid];
    }
    __syncthreads();

    // ---------------- layer 2 ----------------
    #pragma unroll
    for (int j = 0; j < 4; j++) {
        u64 bp; PACK2F(bp, bs[c0 + 2 * j], bs[c0 + 2 * j + 1]);
        acc[0][j] = bp; acc[1][j] = bp;
    }

    #pragma unroll 8
    for (int k = 0; k < D; k++) {
        u64 xx0, xx1;
        PACK_DUP(xx0, Xs[r0][k]);
        PACK_DUP(xx1, Xs[r0 + 1][k]);
        ulonglong2 wa = *(const ulonglong2*)&Ws[k][c0];
        ulonglong2 wb = *(const ulonglong2*)&Ws[k][c0 + 4];
        FMA2(acc[0][0], xx0, wa.x, acc[0][0]); FMA2(acc[1][0], xx1, wa.x, acc[1][0]);
        FMA2(acc[0][1], xx0, wa.y, acc[0][1]); FMA2(acc[1][1], xx1, wa.y, acc[1][1]);
        FMA2(acc[0][2], xx0, wb.x, acc[0][2]); FMA2(acc[1][2], xx1, wb.x, acc[1][2]);
        FMA2(acc[0][3], xx0, wb.y, acc[0][3]); FMA2(acc[1][3], xx1, wb.y, acc[1][3]);
    }

    #pragma unroll
    for (int i = 0; i < 2; i++) {
        int row = row_base + r0 + i;
        if (row < N_NODES) {
            float4 vlo, vhi;
            float lo, hi;
            UNPACK2F(lo, hi, acc[i][0]); vlo.x = leaky(lo); vlo.y = leaky(hi);
            UNPACK2F(lo, hi, acc[i][1]); vlo.z = leaky(lo); vlo.w = leaky(hi);
            UNPACK2F(lo, hi, acc[i][2]); vhi.x = leaky(lo); vhi.y = leaky(hi);
            UNPACK2F(lo, hi, acc[i][3]); vhi.z = leaky(lo); vhi.w = leaky(hi);
            *(float4*)(out + (long long)row * D + c0)     = vlo;
            *(float4*)(out + (long long)row * D + c0 + 4) = vhi;
        }
    }
}

// ---------------------------------------------------------------------------
// launch
// ---------------------------------------------------------------------------
extern "C" void kernel_launch(void* const* d_in, const int* in_sizes, int n_in,
                              void* d_out, int out_size) {
    const float* x   = (const float*)d_in[0];
    const int*   ei  = (const int*)d_in[1];      // int32 (JAX downcasts int64)
    const float* eps = (const float*)d_in[2];
    const float* W1  = (const float*)d_in[3];
    const float* b1  = (const float*)d_in[4];
    const float* W2  = (const float*)d_in[5];
    const float* b2  = (const float*)d_in[6];
    float* out = (float*)d_out;

    float* agg;  cudaGetSymbolAddress((void**)&agg,  g_agg);
    int*   cnt;  cudaGetSymbolAddress((void**)&cnt,  g_count);
    int*   off;  cudaGetSymbolAddress((void**)&off,  g_off);
    int*   endp; cudaGetSymbolAddress((void**)&endp, g_end);
    int*   cur;  cudaGetSymbolAddress((void**)&cur,  g_cur);
    int*   csrs; cudaGetSymbolAddress((void**)&csrs, g_src);
    int*   base; cudaGetSymbolAddress((void**)&base, g_base);

    hist_kernel<<<(N_EDGES + 255) / 256, 256>>>(ei, cnt, base);            // #0
    scan_atomic_kernel<<<N_SBLKS, SCAN_BLK>>>(cnt, off, endp, cur, base);  // #1
    fill_kernel<<<(N_EDGES + 255) / 256, 256>>>(ei, cur, csrs);            // #2
    gather_kernel<<<(N_NODES + 7) / 8, 256>>>((const float2*)x, eps,       // #3
                                              off, endp, csrs, (float2*)agg);
    mlp_kernel<<<(N_NODES + MLP_ROWS - 1) / MLP_ROWS, 256>>>(              // #4
        agg, W1, b1, W2, b2, out);
}

// round 7
// speedup vs baseline: 3.0990x; 1.6195x over previous
#include <cuda_runtime.h>
#include <cuda_bf16.h>
#include <cstdint>

#define N_NODES 100000
#define N_EDGES 1000000
#define D 64

typedef unsigned long long u64;

// ---------------------------------------------------------------------------
// Scratch. g_count starts zero (device globals zero-init) and every
// kernel_launch leaves it zero (scan resets it) -> no zero kernel.
// ---------------------------------------------------------------------------
__device__ float g_agg[N_NODES * D];
__device__ int   g_count[N_NODES];
__device__ int   g_off[N_NODES];
__device__ int   g_end[N_NODES];
__device__ int   g_cur[N_NODES];
__device__ int   g_src[N_EDGES];
__device__ int   g_base;

// ---------------------------------------------------------------------------
// K0: histogram of dst
// ---------------------------------------------------------------------------
__global__ void hist_kernel(const int* __restrict__ ei, int* __restrict__ cnt,
                            int* __restrict__ base) {
    int e = blockIdx.x * blockDim.x + threadIdx.x;
    if (e == 0) *base = 0;
    if (e < N_EDGES) {
        int dst = ei[N_EDGES + e];
        if ((unsigned)dst < N_NODES) atomicAdd(&cnt[dst], 1);
    }
}

// ---------------------------------------------------------------------------
// K1: block scan + atomic base -> off/end/cur; reset cnt.
// ---------------------------------------------------------------------------
#define SCAN_BLK 256
#define N_SBLKS ((N_NODES + SCAN_BLK - 1) / SCAN_BLK)

__global__ __launch_bounds__(SCAN_BLK)
void scan_atomic_kernel(int* __restrict__ cnt, int* __restrict__ off,
                        int* __restrict__ endp, int* __restrict__ cur,
                        int* __restrict__ base) {
    __shared__ int sm[SCAN_BLK];
    __shared__ int sbase;
    int i = blockIdx.x * SCAN_BLK + threadIdx.x;
    int t = threadIdx.x;
    int v = (i < N_NODES) ? cnt[i] : 0;
    sm[t] = v;
    for (int ofs = 1; ofs < SCAN_BLK; ofs <<= 1) {
        __syncthreads();
        int u = (t >= ofs) ? sm[t - ofs] : 0;
        __syncthreads();
        sm[t] += u;
    }
    __syncthreads();
    if (t == SCAN_BLK - 1) sbase = atomicAdd(base, sm[SCAN_BLK - 1]);
    __syncthreads();
    if (i < N_NODES) {
        int incl = sbase + sm[t];
        int st = incl - v;
        off[i]  = st;
        cur[i]  = st;
        endp[i] = incl;
        cnt[i]  = 0;
    }
}

// ---------------------------------------------------------------------------
// K2: fill CSR src lists
// ---------------------------------------------------------------------------
__global__ void fill_kernel(const int* __restrict__ ei,
                            int* __restrict__ cur,
                            int* __restrict__ csr_src) {
    int e = blockIdx.x * blockDim.x + threadIdx.x;
    if (e < N_EDGES) {
        int src = ei[e];
        int dst = ei[N_EDGES + e];
        if ((unsigned)src >= N_NODES || (unsigned)dst >= N_NODES) return;
        int pos = atomicAdd(&cur[dst], 1);
        csr_src[pos] = src;
    }
}

// ---------------------------------------------------------------------------
// K3: gather + fused (1+eps)*x (unchanged; measured 32us)
// ---------------------------------------------------------------------------
__global__ __launch_bounds__(256)
void gather_kernel(const float2* __restrict__ x2,
                   const float* __restrict__ eps,
                   const int* __restrict__ off,
                   const int* __restrict__ endp,
                   const int* __restrict__ csr_src,
                   float2* __restrict__ agg2) {
    int warp = (blockIdx.x * blockDim.x + threadIdx.x) >> 5;
    int lane = threadIdx.x & 31;
    if (warp >= N_NODES) return;

    float s = 1.0f + *eps;
    unsigned self = (unsigned)warp * 32u + (unsigned)lane;
    float2 v = x2[self];
    float ax = s * v.x, ay = s * v.y;

    int start = off[warp];
    int end   = endp[warp];

    for (int base = start; base < end; base += 32) {
        int n = min(32, end - base);
        int myidx = (lane < n) ? csr_src[base + lane] : 0;
        for (int j = 0; j < n; j += 4) {
            int s0 = __shfl_sync(0xffffffffu, myidx, j);
            int s1 = __shfl_sync(0xffffffffu, myidx, j + 1);
            int s2 = __shfl_sync(0xffffffffu, myidx, j + 2);
            int s3 = __shfl_sync(0xffffffffu, myidx, j + 3);
            float2 n0 = x2[(unsigned)s0 * 32u + lane];
            float2 n1 = x2[(unsigned)s1 * 32u + lane];
            float2 n2 = x2[(unsigned)s2 * 32u + lane];
            float2 n3 = x2[(unsigned)s3 * 32u + lane];
            ax += n0.x; ay += n0.y;
            if (j + 1 < n) { ax += n1.x; ay += n1.y; }
            if (j + 2 < n) { ax += n2.x; ay += n2.y; }
            if (j + 3 < n) { ax += n3.x; ay += n3.y; }
        }
    }
    float2 o; o.x = ax; o.y = ay;
    agg2[self] = o;
}

// ---------------------------------------------------------------------------
// K4: fused 2-layer MLP. 128 threads, 64 rows/block.
// Thread tile: 4 rows x 8 cols, cols = {4cg..4cg+3} U {32+4cg..35+4cg}
//  -> each weight LDS.128 covers banks 0-31 exactly once (conflict-free,
//     rg-duplicates are broadcast). 2 weight wf + 4 x-broadcast wf per k
//     per warp for 4x8x32 outputs.
// ---------------------------------------------------------------------------
#define MLP_ROWS 64
#define MLP_THREADS 128
#define XS_STRIDE 66

__device__ __forceinline__ float leaky(float v) {
    return fmaxf(v, 0.01f * v);
}

#define FMA2(d, a, b, c) \
    asm("fma.rn.f32x2 %0, %1, %2, %3;" : "=l"(d) : "l"(a), "l"(b), "l"(c))
#define PACK_DUP(out, f) \
    asm("mov.b64 %0, {%1, %1};" : "=l"(out) : "r"(__float_as_uint(f)))
#define PACK2F(out, lo, hi) \
    asm("mov.b64 %0, {%1, %2};" : "=l"(out) : "r"(__float_as_uint(lo)), "r"(__float_as_uint(hi)))
#define UNPACK2F(lo, hi, in) \
    { unsigned _l, _h; asm("mov.b64 {%0, %1}, %2;" : "=r"(_l), "=r"(_h) : "l"(in)); \
      lo = __uint_as_float(_l); hi = __uint_as_float(_h); }

__global__ __launch_bounds__(MLP_THREADS)
void mlp_kernel(const float* __restrict__ agg,
                const float* __restrict__ W1, const float* __restrict__ b1,
                const float* __restrict__ W2, const float* __restrict__ b2,
                float* __restrict__ out) {
    __shared__ float Xs[MLP_ROWS][XS_STRIDE];   // 16.9 KB
    __shared__ float Ws[D][D];                  // 16 KB
    __shared__ float bs[D];

    const int tid = threadIdx.x;
    const int cg  = tid & 7;          // 8 col groups
    const int rg  = tid >> 3;         // 16 row groups x 4 rows = 64 rows
    const int row_base = blockIdx.x * MLP_ROWS;
    const int r0 = rg * 4;
    const int ca = cg * 4;            // quad A cols
    const int cb = 32 + cg * 4;       // quad B cols

    // --- load X tile (float2, coalesced; stride-66 rows are 8B aligned) ---
    {
        const float2* src = (const float2*)(agg + (long long)row_base * D);
        for (int idx = tid; idx < MLP_ROWS * (D / 2); idx += MLP_THREADS) {
            int r = idx >> 5;
            int p = idx & 31;
            float2 v;
            if (row_base + r < N_NODES) v = src[r * 32 + p];
            else { v.x = 0.f; v.y = 0.f; }
            Xs[r][p * 2]     = v.x;
            Xs[r][p * 2 + 1] = v.y;
        }
    }
    // --- load W1, b1 ---
    {
        const float4* w = (const float4*)W1;
        float4* ws = (float4*)&Ws[0][0];
        for (int idx = tid; idx < D * D / 4; idx += MLP_THREADS) ws[idx] = w[idx];
        if (tid < D) bs[tid] = b1[tid];
    }
    __syncthreads();

    // ---------------- layer 1 ----------------
    // acc[i][0..1] = quad A pairs, acc[i][2..3] = quad B pairs
    u64 acc[4][4];
    {
        u64 a0, a1, b0, b1p;
        PACK2F(a0, bs[ca],     bs[ca + 1]);
        PACK2F(a1, bs[ca + 2], bs[ca + 3]);
        PACK2F(b0, bs[cb],     bs[cb + 1]);
        PACK2F(b1p, bs[cb + 2], bs[cb + 3]);
        #pragma unroll
        for (int i = 0; i < 4; i++) {
            acc[i][0] = a0; acc[i][1] = a1; acc[i][2] = b0; acc[i][3] = b1p;
        }
    }

    #pragma unroll 4
    for (int k = 0; k < D; k++) {
        ulonglong2 wa = *(const ulonglong2*)&Ws[k][ca];
        ulonglong2 wb = *(const ulonglong2*)&Ws[k][cb];
        #pragma unroll
        for (int i = 0; i < 4; i++) {
            u64 xx; PACK_DUP(xx, Xs[r0 + i][k]);
            FMA2(acc[i][0], xx, wa.x, acc[i][0]);
            FMA2(acc[i][1], xx, wa.y, acc[i][1]);
            FMA2(acc[i][2], xx, wb.x, acc[i][2]);
            FMA2(acc[i][3], xx, wb.y, acc[i][3]);
        }
    }
    __syncthreads();

    // leaky + write back into Xs
    #pragma unroll
    for (int i = 0; i < 4; i++) {
        float lo, hi;
        UNPACK2F(lo, hi, acc[i][0]); Xs[r0 + i][ca]     = leaky(lo); Xs[r0 + i][ca + 1] = leaky(hi);
        UNPACK2F(lo, hi, acc[i][1]); Xs[r0 + i][ca + 2] = leaky(lo); Xs[r0 + i][ca + 3] = leaky(hi);
        UNPACK2F(lo, hi, acc[i][2]); Xs[r0 + i][cb]     = leaky(lo); Xs[r0 + i][cb + 1] = leaky(hi);
        UNPACK2F(lo, hi, acc[i][3]); Xs[r0 + i][cb + 2] = leaky(lo); Xs[r0 + i][cb + 3] = leaky(hi);
    }

    // --- load W2, b2 ---
    {
        const float4* w = (const float4*)W2;
        float4* ws = (float4*)&Ws[0][0];
        for (int idx = tid; idx < D * D / 4; idx += MLP_THREADS) ws[idx] = w[idx];
        if (tid < D) bs[tid] = b2[tid];
    }
    __syncthreads();

    // ---------------- layer 2 ----------------
    {
        u64 a0, a1, b0, b1p;
        PACK2F(a0, bs[ca],     bs[ca + 1]);
        PACK2F(a1, bs[ca + 2], bs[ca + 3]);
        PACK2F(b0, bs[cb],     bs[cb + 1]);
        PACK2F(b1p, bs[cb + 2], bs[cb + 3]);
        #pragma unroll
        for (int i = 0; i < 4; i++) {
            acc[i][0] = a0; acc[i][1] = a1; acc[i][2] = b0; acc[i][3] = b1p;
        }
    }

    #pragma unroll 4
    for (int k = 0; k < D; k++) {
        ulonglong2 wa = *(const ulonglong2*)&Ws[k][ca];
        ulonglong2 wb = *(const ulonglong2*)&Ws[k][cb];
        #pragma unroll
        for (int i = 0; i < 4; i++) {
            u64 xx; PACK_DUP(xx, Xs[r0 + i][k]);
            FMA2(acc[i][0], xx, wa.x, acc[i][0]);
            FMA2(acc[i][1], xx, wa.y, acc[i][1]);
            FMA2(acc[i][2], xx, wb.x, acc[i][2]);
            FMA2(acc[i][3], xx, wb.y, acc[i][3]);
        }
    }

    // --- store output: two float4 quads per row per thread ---
    #pragma unroll
    for (int i = 0; i < 4; i++) {
        int row = row_base + r0 + i;
        if (row < N_NODES) {
            float lo, hi;
            float4 va, vb;
            UNPACK2F(lo, hi, acc[i][0]); va.x = leaky(lo); va.y = leaky(hi);
            UNPACK2F(lo, hi, acc[i][1]); va.z = leaky(lo); va.w = leaky(hi);
            UNPACK2F(lo, hi, acc[i][2]); vb.x = leaky(lo); vb.y = leaky(hi);
            UNPACK2F(lo, hi, acc[i][3]); vb.z = leaky(lo); vb.w = leaky(hi);
            *(float4*)(out + (long long)row * D + ca) = va;
            *(float4*)(out + (long long)row * D + cb) = vb;
        }
    }
}

// ---------------------------------------------------------------------------
// launch
// ---------------------------------------------------------------------------
extern "C" void kernel_launch(void* const* d_in, const int* in_sizes, int n_in,
                              void* d_out, int out_size) {
    const float* x   = (const float*)d_in[0];
    const int*   ei  = (const int*)d_in[1];      // int32 (JAX downcasts int64)
    const float* eps = (const float*)d_in[2];
    const float* W1  = (const float*)d_in[3];
    const float* b1  = (const float*)d_in[4];
    const float* W2  = (const float*)d_in[5];
    const float* b2  = (const float*)d_in[6];
    float* out = (float*)d_out;

    float* agg;  cudaGetSymbolAddress((void**)&agg,  g_agg);
    int*   cnt;  cudaGetSymbolAddress((void**)&cnt,  g_count);
    int*   off;  cudaGetSymbolAddress((void**)&off,  g_off);
    int*   endp; cudaGetSymbolAddress((void**)&endp, g_end);
    int*   cur;  cudaGetSymbolAddress((void**)&cur,  g_cur);
    int*   csrs; cudaGetSymbolAddress((void**)&csrs, g_src);
    int*   base; cudaGetSymbolAddress((void**)&base, g_base);

    hist_kernel<<<(N_EDGES + 255) / 256, 256>>>(ei, cnt, base);            // #0
    scan_atomic_kernel<<<N_SBLKS, SCAN_BLK>>>(cnt, off, endp, cur, base);  // #1
    fill_kernel<<<(N_EDGES + 255) / 256, 256>>>(ei, cur, csrs);            // #2
    gather_kernel<<<(N_NODES + 7) / 8, 256>>>((const float2*)x, eps,       // #3
                                              off, endp, csrs, (float2*)agg);
    mlp_kernel<<<(N_NODES + MLP_ROWS - 1) / MLP_ROWS, MLP_THREADS>>>(      // #4
        agg, W1, b1, W2, b2, out);
}